// round 6
// baseline (speedup 1.0000x reference)
#include <cuda_runtime.h>
#include <cuda_bf16.h>
#include <math.h>
#include <stdint.h>

#define BATCH 4
#define SLEN 2048
#define DM 2048
#define NHEAD 16
#define HS 128
#define EPROJ (3 * DM)
#define KDIM 2048

// Scratch (no allocations allowed)
__device__ __nv_bfloat16 g_qhi[(size_t)BATCH * NHEAD * SLEN * HS];
__device__ __nv_bfloat16 g_qlo[(size_t)BATCH * NHEAD * SLEN * HS];
__device__ __nv_bfloat16 g_khi[(size_t)BATCH * NHEAD * SLEN * HS];
__device__ __nv_bfloat16 g_klo[(size_t)BATCH * NHEAD * SLEN * HS];
__device__ __nv_bfloat16 g_vhi[(size_t)BATCH * NHEAD * SLEN * HS];
__device__ __nv_bfloat16 g_vlo[(size_t)BATCH * NHEAD * SLEN * HS];
__device__ __nv_bfloat16 g_xhi[(size_t)BATCH * SLEN * DM];
__device__ __nv_bfloat16 g_xlo[(size_t)BATCH * SLEN * DM];
__device__ __nv_bfloat16 g_wphi[(size_t)EPROJ * DM];
__device__ __nv_bfloat16 g_wplo[(size_t)EPROJ * DM];
__device__ __nv_bfloat16 g_wfhi[(size_t)DM * DM];
__device__ __nv_bfloat16 g_wflo[(size_t)DM * DM];
__device__ __nv_bfloat16 g_athi[(size_t)BATCH * SLEN * DM];
__device__ __nv_bfloat16 g_atlo[(size_t)BATCH * SLEN * DM];

// ---------------------------------------------------------------------------
// helpers (non-arch-specific PTX only)
// ---------------------------------------------------------------------------
__device__ __forceinline__ uint32_t smem_u32(const void* p) {
    uint32_t a;
    asm("{ .reg .u64 t; cvta.to.shared.u64 t, %1; cvt.u32.u64 %0, t; }"
        : "=r"(a) : "l"(p));
    return a;
}

__device__ __forceinline__ void ldm_x4(uint32_t* r, uint32_t addr) {
    asm volatile("ldmatrix.sync.aligned.m8n8.x4.shared.b16 {%0,%1,%2,%3}, [%4];"
                 : "=r"(r[0]), "=r"(r[1]), "=r"(r[2]), "=r"(r[3]) : "r"(addr));
}

__device__ __forceinline__ void ldm_x4_t(uint32_t* r, uint32_t addr) {
    asm volatile("ldmatrix.sync.aligned.m8n8.x4.trans.shared.b16 {%0,%1,%2,%3}, [%4];"
                 : "=r"(r[0]), "=r"(r[1]), "=r"(r[2]), "=r"(r[3]) : "r"(addr));
}

__device__ __forceinline__ void mma_bf16(float* c, const uint32_t* a,
                                         const uint32_t* b) {
    asm volatile(
        "mma.sync.aligned.m16n8k16.row.col.f32.bf16.bf16.f32 "
        "{%0,%1,%2,%3}, {%4,%5,%6,%7}, {%8,%9}, {%0,%1,%2,%3};"
        : "+f"(c[0]), "+f"(c[1]), "+f"(c[2]), "+f"(c[3])
        : "r"(a[0]), "r"(a[1]), "r"(a[2]), "r"(a[3]), "r"(b[0]), "r"(b[1]));
}

#define CP_ASYNC16(dst, src) \
    asm volatile("cp.async.cg.shared.global [%0], [%1], 16;" \
                 :: "r"(dst), "l"(src))
#define CP_COMMIT() asm volatile("cp.async.commit_group;" ::: "memory")
#define CP_WAIT1() asm volatile("cp.async.wait_group 1;" ::: "memory")
#define CP_WAIT0() asm volatile("cp.async.wait_group 0;" ::: "memory")

__device__ __forceinline__ void split4(float4 v, uint2& hi, uint2& lo) {
    __nv_bfloat162 h01 = __floats2bfloat162_rn(v.x, v.y);
    __nv_bfloat162 h23 = __floats2bfloat162_rn(v.z, v.w);
    uint32_t u01 = *(uint32_t*)&h01, u23 = *(uint32_t*)&h23;
    float fx = __uint_as_float(u01 << 16);
    float fy = __uint_as_float(u01 & 0xffff0000u);
    float fz = __uint_as_float(u23 << 16);
    float fw = __uint_as_float(u23 & 0xffff0000u);
    __nv_bfloat162 l01 = __floats2bfloat162_rn(v.x - fx, v.y - fy);
    __nv_bfloat162 l23 = __floats2bfloat162_rn(v.z - fz, v.w - fw);
    hi = make_uint2(u01, u23);
    lo = make_uint2(*(uint32_t*)&l01, *(uint32_t*)&l23);
}

// fp32 -> bf16 hi/lo pre-split
__global__ __launch_bounds__(256) void split_kernel(
    const float4* __restrict__ src, uint2* __restrict__ hi,
    uint2* __restrict__ lo, int n4)
{
    int i = blockIdx.x * 256 + threadIdx.x;
    const int stride = gridDim.x * 256;
    for (; i < n4; i += stride) {
        uint2 h, l;
        split4(src[i], h, l);
        hi[i] = h;
        lo[i] = l;
    }
}

// ---------------------------------------------------------------------------
// Pipelined bf16-split GEMM: C = A * W^T + bias (pre-split hi/lo operands).
// CTA 128x128, 8 warps (2Mx4N), warp 64x32, BK=32, 3-stage cp.async,
// 64B smem rows with arithmetic swizzle (conflict-free ldmatrix), occ 2.
// EPI==1: QKV epilogue (q scaled hi/lo; k/v fp32 d_out + hi/lo scratch).
// EPI==2: dense fp32 C.
// ---------------------------------------------------------------------------
#define ARR_B 8192                     // 128 rows * 64 B
#define STAGE_B (4 * ARR_B)            // Ahi|Alo|Whi|Wlo = 32768 B
#define NSTAGE 3
#define GEMM_SMEM (NSTAGE * STAGE_B)   // 98304 B
#define NCHUNK (KDIM / 32)             // 64

// byte offset of 16B chunk c (0..3) in row (row, 64B pitch), swizzled
__device__ __forceinline__ uint32_t gswz(int row, int c) {
    return (uint32_t)((row << 6) + (((c + (row >> 1)) & 3) << 4));
}

template <int EPI>
__global__ __launch_bounds__(256, 2) void gemm_bf_kernel(
    const __nv_bfloat16* __restrict__ Ahi, const __nv_bfloat16* __restrict__ Alo,
    const __nv_bfloat16* __restrict__ Whi, const __nv_bfloat16* __restrict__ Wlo,
    const float* __restrict__ bias, float* __restrict__ C,
    float* __restrict__ kout, float* __restrict__ vout)
{
    extern __shared__ __align__(16) char smem[];
    const uint32_t sbase = smem_u32(smem);

    const int tid = threadIdx.x;
    const int wid = tid >> 5;
    const int lid = tid & 31;
    const int m0 = blockIdx.y * 128;
    const int n0 = blockIdx.x * 128;
    const int warpM = wid >> 2;
    const int warpN = wid & 3;

    // cp.async mapping: arr = tid>>6 (Ahi/Alo/Whi/Wlo), 2 rows x 4 chunks each
    const int arr = tid >> 6;
    const int r0 = (tid & 63) << 1;
    const __nv_bfloat16* srcb =
        ((arr == 0) ? Ahi : (arr == 1) ? Alo : (arr == 2) ? Whi : Wlo) +
        (size_t)(((arr < 2) ? m0 : n0) + r0) * KDIM;
    const uint32_t dst0 = sbase + (uint32_t)(arr * ARR_B);
    const uint32_t sw0 = gswz(r0, 0), sw1 = gswz(r0, 1);
    const uint32_t sw2 = gswz(r0, 2), sw3 = gswz(r0, 3);
    const uint32_t tw0 = gswz(r0 + 1, 0), tw1 = gswz(r0 + 1, 1);
    const uint32_t tw2 = gswz(r0 + 1, 2), tw3 = gswz(r0 + 1, 3);

    // ldmatrix components
    const int q = lid >> 3, rr = lid & 7;
    const int aRow = warpM * 64 + (q & 1) * 8 + rr;   // + mi*16
    const int aCh = q >> 1;                           // + ks*2
    const int bRow = warpN * 32 + (q >> 1) * 8 + rr;  // + pj*16
    const int bCh = q & 1;                            // + ks*2

    float acc[4][4][4];
#pragma unroll
    for (int i = 0; i < 4; i++)
#pragma unroll
        for (int j = 0; j < 4; j++)
#pragma unroll
            for (int r = 0; r < 4; r++) acc[i][j][r] = 0.f;

    auto issue = [&](int c, int stg) {
        const __nv_bfloat16* sp = srcb + c * 32;
        const uint32_t d = dst0 + (uint32_t)(stg * STAGE_B);
        CP_ASYNC16(d + sw0, sp);
        CP_ASYNC16(d + sw1, sp + 8);
        CP_ASYNC16(d + sw2, sp + 16);
        CP_ASYNC16(d + sw3, sp + 24);
        CP_ASYNC16(d + tw0, sp + KDIM);
        CP_ASYNC16(d + tw1, sp + KDIM + 8);
        CP_ASYNC16(d + tw2, sp + KDIM + 16);
        CP_ASYNC16(d + tw3, sp + KDIM + 24);
    };

    issue(0, 0); CP_COMMIT();
    issue(1, 1); CP_COMMIT();

    int stage = 0;
    for (int c = 0; c < NCHUNK; c++) {
        if (c + 2 < NCHUNK) { CP_WAIT1(); } else { CP_WAIT0(); }
        __syncthreads();
        if (c + 2 < NCHUNK) {
            int s2 = stage + 2; if (s2 >= NSTAGE) s2 -= NSTAGE;
            issue(c + 2, s2);
        }
        CP_COMMIT();

        const uint32_t st = sbase + (uint32_t)(stage * STAGE_B);
#pragma unroll
        for (int ks = 0; ks < 2; ks++) {
            uint32_t ah[4][4], al[4][4], bh[2][4], bl[2][4];
#pragma unroll
            for (int mi = 0; mi < 4; mi++) {
                const uint32_t off = gswz(aRow + mi * 16, ks * 2 + aCh);
                ldm_x4(ah[mi], st + off);
                ldm_x4(al[mi], st + ARR_B + off);
            }
#pragma unroll
            for (int pj = 0; pj < 2; pj++) {
                const uint32_t off = gswz(bRow + pj * 16, ks * 2 + bCh);
                ldm_x4(bh[pj], st + 2 * ARR_B + off);
                ldm_x4(bl[pj], st + 3 * ARR_B + off);
            }
#pragma unroll
            for (int mi = 0; mi < 4; mi++)
#pragma unroll
                for (int nj = 0; nj < 4; nj++) {
                    const uint32_t* bhp = &bh[nj >> 1][(nj & 1) * 2];
                    const uint32_t* blp = &bl[nj >> 1][(nj & 1) * 2];
                    mma_bf16(acc[mi][nj], ah[mi], bhp);
                    mma_bf16(acc[mi][nj], al[mi], bhp);
                    mma_bf16(acc[mi][nj], ah[mi], blp);
                }
        }
        if (++stage == NSTAGE) stage = 0;
        __syncthreads();
    }

    // Epilogue
    const int t4 = lid >> 2;
    const int t2 = (lid & 3) << 1;
    if (EPI == 1) {
        const int seg = n0 >> 7;
        const int h = (int)((unsigned)seg / 3u);
        const int which = seg - h * 3;
        __nv_bfloat16 *hib, *lob;
        float* fpb = nullptr;
        if (which == 0)      { hib = g_qhi; lob = g_qlo; }
        else if (which == 1) { hib = g_khi; lob = g_klo; fpb = kout; }
        else                 { hib = g_vhi; lob = g_vlo; fpb = vout; }
        const float scl = (which == 0) ? 0.08838834764831845f : 1.0f;
#pragma unroll
        for (int mi = 0; mi < 4; mi++) {
            const int mrow = m0 + warpM * 64 + mi * 16 + t4;
            const int bb = mrow >> 11, ss = mrow & 2047;
            const size_t i0 = (((size_t)(bb * NHEAD + h)) * SLEN + ss) * HS;
            const size_t i1 = i0 + 8 * HS;
#pragma unroll
            for (int nj = 0; nj < 4; nj++) {
                const int col = warpN * 32 + nj * 8 + t2;
                const float2 bv = *(const float2*)(bias + n0 + col);
                float x0 = acc[mi][nj][0] + bv.x, x1 = acc[mi][nj][1] + bv.y;
                float y0 = acc[mi][nj][2] + bv.x, y1 = acc[mi][nj][3] + bv.y;
                if (which != 0) {
                    *(float2*)(fpb + i0 + col) = make_float2(x0, x1);
                    *(float2*)(fpb + i1 + col) = make_float2(y0, y1);
                }
                x0 *= scl; x1 *= scl; y0 *= scl; y1 *= scl;
                __nv_bfloat162 hx = __floats2bfloat162_rn(x0, x1);
                float2 hf = __bfloat1622float2(hx);
                __nv_bfloat162 lx = __floats2bfloat162_rn(x0 - hf.x, x1 - hf.y);
                __nv_bfloat162 hy = __floats2bfloat162_rn(y0, y1);
                float2 hg = __bfloat1622float2(hy);
                __nv_bfloat162 ly = __floats2bfloat162_rn(y0 - hg.x, y1 - hg.y);
                *(__nv_bfloat162*)(hib + i0 + col) = hx;
                *(__nv_bfloat162*)(lob + i0 + col) = lx;
                *(__nv_bfloat162*)(hib + i1 + col) = hy;
                *(__nv_bfloat162*)(lob + i1 + col) = ly;
            }
        }
    } else {
#pragma unroll
        for (int mi = 0; mi < 4; mi++) {
            const int mrow = m0 + warpM * 64 + mi * 16 + t4;
            float* d0 = C + (size_t)mrow * DM + n0;
            float* d1 = C + (size_t)(mrow + 8) * DM + n0;
#pragma unroll
            for (int nj = 0; nj < 4; nj++) {
                const int col = warpN * 32 + nj * 8 + t2;
                const float2 bv = *(const float2*)(bias + n0 + col);
                *(float2*)(d0 + col) =
                    make_float2(acc[mi][nj][0] + bv.x, acc[mi][nj][1] + bv.y);
                *(float2*)(d1 + col) =
                    make_float2(acc[mi][nj][2] + bv.x, acc[mi][nj][3] + bv.y);
            }
        }
    }
}

// ---------------------------------------------------------------------------
// Flash attention via mma.sync (FA2-style), causal, bf16 2-way split on both
// QK^T and PV. CTA = 128 q-rows x one (b*H+h); epilogue -> bf16 hi/lo.
// ---------------------------------------------------------------------------
#define QT 128
#define KT 64
#define Q_BYTES 32768
#define KV_ARR 16384
#define KV_BUF (4 * KV_ARR)
#define ATT_SMEM (2 * Q_BYTES + 2 * KV_BUF)  // 196608

__device__ __forceinline__ uint32_t swz(int row, int chunk) {
    return (uint32_t)(row * 256 + ((chunk ^ (row & 7)) << 4));
}

__global__ __launch_bounds__(256) void attn_mma_kernel()
{
    extern __shared__ __align__(16) char sm[];
    const uint32_t sb = smem_u32(sm);
    const int tid = threadIdx.x, wid = tid >> 5, lane = tid & 31;
    const int qb = blockIdx.x, bh = blockIdx.y;
    const int q0 = qb * QT;
    const int nkt = 2 * qb + 2;

    const size_t qoff = ((size_t)bh * SLEN + q0) * HS;
    const size_t kvoff = (size_t)bh * SLEN * HS;

    {
        const int half = tid >> 7;
        const __nv_bfloat16* src = (half ? g_qlo : g_qhi) + qoff;
        char* base = sm + half * Q_BYTES;
        int rc = tid & 127;
#pragma unroll
        for (int t = 0; t < 16; t++, rc += 128) {
            const int row = rc >> 4, c = rc & 15;
            uint4 v = *(const uint4*)(src + row * HS + c * 8);
            *(uint4*)(base + swz(row, c)) = v;
        }
    }

    const int karr = tid >> 6;
    const __nv_bfloat16* ksrc =
        ((karr == 0) ? g_khi : (karr == 1) ? g_klo : (karr == 2) ? g_vhi : g_vlo)
        + kvoff;
    const uint32_t kdstArr = sb + 2 * Q_BYTES + (uint32_t)(karr * KV_ARR);

    auto kv_issue = [&](int kt, int bf) {
        const __nv_bfloat16* s = ksrc + (size_t)kt * KT * HS;
        const uint32_t dbase = kdstArr + (uint32_t)(bf * KV_BUF);
        int rc = tid & 63;
#pragma unroll
        for (int t = 0; t < 16; t++, rc += 64) {
            const int row = rc >> 4, c = rc & 15;
            CP_ASYNC16(dbase + swz(row, c), s + row * HS + c * 8);
        }
    };

    kv_issue(0, 0);
    CP_COMMIT();

    float o[16][4];
#pragma unroll
    for (int t = 0; t < 16; t++)
#pragma unroll
        for (int r = 0; r < 4; r++) o[t][r] = 0.f;
    float m0r = -INFINITY, m1r = -INFINITY, l0r = 0.f, l1r = 0.f;

    const int aRow = wid * 16 + (lane & 7) + ((lane >> 3) & 1) * 8;
    const int aCh = lane >> 4;
    const int bRowK = (lane & 7) + (lane >> 4) * 8;
    const int bChK = (lane >> 3) & 1;
    const int vRow = (lane & 7) + ((lane >> 3) & 1) * 8;
    const int vCh = lane >> 4;

    for (int kt = 0; kt < nkt; kt++) {
        if (kt + 1 < nkt) {
            kv_issue(kt + 1, (kt + 1) & 1);
            CP_COMMIT();
            CP_WAIT1();
        } else {
            CP_WAIT0();
        }
        __syncthreads();

        const uint32_t kvb = sb + 2 * Q_BYTES + (uint32_t)((kt & 1) * KV_BUF);

        float s[8][4];
#pragma unroll
        for (int nj = 0; nj < 8; nj++)
#pragma unroll
            for (int r = 0; r < 4; r++) s[nj][r] = 0.f;

#pragma unroll
        for (int ks = 0; ks < 8; ks++) {
            uint32_t qh[4], ql[4];
            const uint32_t qa = sb + swz(aRow, 2 * ks + aCh);
            ldm_x4(qh, qa);
            ldm_x4(ql, qa + Q_BYTES);
#pragma unroll
            for (int njp = 0; njp < 4; njp++) {
                uint32_t kh[4], kl[4];
                const uint32_t ka = kvb + swz(njp * 16 + bRowK, 2 * ks + bChK);
                ldm_x4(kh, ka);
                ldm_x4(kl, ka + KV_ARR);
                mma_bf16(s[2 * njp], qh, kh);
                mma_bf16(s[2 * njp], ql, kh);
                mma_bf16(s[2 * njp], qh, kl);
                mma_bf16(s[2 * njp + 1], qh, kh + 2);
                mma_bf16(s[2 * njp + 1], ql, kh + 2);
                mma_bf16(s[2 * njp + 1], qh, kl + 2);
            }
        }

        const int r0g = q0 + wid * 16 + (lane >> 2);
        if (kt >= 2 * qb) {
            const int cb = kt * KT + (lane & 3) * 2;
#pragma unroll
            for (int nj = 0; nj < 8; nj++) {
                const int c0 = cb + nj * 8;
                if (c0 > r0g)         s[nj][0] = -INFINITY;
                if (c0 + 1 > r0g)     s[nj][1] = -INFINITY;
                if (c0 > r0g + 8)     s[nj][2] = -INFINITY;
                if (c0 + 1 > r0g + 8) s[nj][3] = -INFINITY;
            }
        }

        float tm0 = -INFINITY, tm1 = -INFINITY;
#pragma unroll
        for (int nj = 0; nj < 8; nj++) {
            tm0 = fmaxf(tm0, fmaxf(s[nj][0], s[nj][1]));
            tm1 = fmaxf(tm1, fmaxf(s[nj][2], s[nj][3]));
        }
        tm0 = fmaxf(tm0, __shfl_xor_sync(0xffffffffu, tm0, 1));
        tm0 = fmaxf(tm0, __shfl_xor_sync(0xffffffffu, tm0, 2));
        tm1 = fmaxf(tm1, __shfl_xor_sync(0xffffffffu, tm1, 1));
        tm1 = fmaxf(tm1, __shfl_xor_sync(0xffffffffu, tm1, 2));
        const float mn0 = fmaxf(m0r, tm0), mn1 = fmaxf(m1r, tm1);
        const float a0 = __expf(m0r - mn0), a1 = __expf(m1r - mn1);
        m0r = mn0; m1r = mn1;

        float ls0 = 0.f, ls1 = 0.f;
        uint32_t pah[4][4], pal[4][4];
#pragma unroll
        for (int nj = 0; nj < 8; nj++) {
            const float p0 = __expf(s[nj][0] - mn0);
            const float p1 = __expf(s[nj][1] - mn0);
            const float p2 = __expf(s[nj][2] - mn1);
            const float p3 = __expf(s[nj][3] - mn1);
            ls0 += p0 + p1;
            ls1 += p2 + p3;
            __nv_bfloat162 h01 = __floats2bfloat162_rn(p0, p1);
            float2 hf01 = __bfloat1622float2(h01);
            __nv_bfloat162 lo01 = __floats2bfloat162_rn(p0 - hf01.x, p1 - hf01.y);
            __nv_bfloat162 h23 = __floats2bfloat162_rn(p2, p3);
            float2 hf23 = __bfloat1622float2(h23);
            __nv_bfloat162 lo23 = __floats2bfloat162_rn(p2 - hf23.x, p3 - hf23.y);
            const int j = nj >> 1, e = (nj & 1) * 2;
            pah[j][e] = *(uint32_t*)&h01;
            pah[j][e + 1] = *(uint32_t*)&h23;
            pal[j][e] = *(uint32_t*)&lo01;
            pal[j][e + 1] = *(uint32_t*)&lo23;
        }
        ls0 += __shfl_xor_sync(0xffffffffu, ls0, 1);
        ls0 += __shfl_xor_sync(0xffffffffu, ls0, 2);
        ls1 += __shfl_xor_sync(0xffffffffu, ls1, 1);
        ls1 += __shfl_xor_sync(0xffffffffu, ls1, 2);
        l0r = l0r * a0 + ls0;
        l1r = l1r * a1 + ls1;

#pragma unroll
        for (int t = 0; t < 16; t++) {
            o[t][0] *= a0; o[t][1] *= a0;
            o[t][2] *= a1; o[t][3] *= a1;
        }

#pragma unroll
        for (int j = 0; j < 4; j++) {
#pragma unroll
            for (int nd = 0; nd < 8; nd++) {
                uint32_t vh[4], vl[4];
                const uint32_t va =
                    kvb + 2 * KV_ARR + swz(j * 16 + vRow, 2 * nd + vCh);
                ldm_x4_t(vh, va);
                ldm_x4_t(vl, va + KV_ARR);
                mma_bf16(o[2 * nd], pah[j], vh);
                mma_bf16(o[2 * nd], pal[j], vh);
                mma_bf16(o[2 * nd], pah[j], vl);
                mma_bf16(o[2 * nd + 1], pah[j], vh + 2);
                mma_bf16(o[2 * nd + 1], pal[j], vh + 2);
                mma_bf16(o[2 * nd + 1], pah[j], vl + 2);
            }
        }
        __syncthreads();
    }

    // write attn_o as bf16 hi/lo directly (consumed by FF GEMM)
    const float inv0 = 1.f / l0r, inv1 = 1.f / l1r;
    const int b = bh >> 4, h = bh & 15;
    const int r0g = q0 + wid * 16 + (lane >> 2);
    const size_t base0 =
        ((size_t)(b * SLEN + r0g)) * DM + h * HS + (lane & 3) * 2;
    const size_t base1 = base0 + (size_t)8 * DM;
#pragma unroll
    for (int t = 0; t < 16; t++) {
        float v0 = o[t][0] * inv0, v1 = o[t][1] * inv0;
        float w0 = o[t][2] * inv1, w1 = o[t][3] * inv1;
        __nv_bfloat162 h0 = __floats2bfloat162_rn(v0, v1);
        float2 f0 = __bfloat1622float2(h0);
        __nv_bfloat162 l0 = __floats2bfloat162_rn(v0 - f0.x, v1 - f0.y);
        __nv_bfloat162 h1 = __floats2bfloat162_rn(w0, w1);
        float2 f1 = __bfloat1622float2(h1);
        __nv_bfloat162 l1 = __floats2bfloat162_rn(w0 - f1.x, w1 - f1.y);
        *(__nv_bfloat162*)(g_athi + base0 + t * 8) = h0;
        *(__nv_bfloat162*)(g_atlo + base0 + t * 8) = l0;
        *(__nv_bfloat162*)(g_athi + base1 + t * 8) = h1;
        *(__nv_bfloat162*)(g_atlo + base1 + t * 8) = l1;
    }
}

// ---------------------------------------------------------------------------
extern "C" void kernel_launch(void* const* d_in, const int* in_sizes, int n_in,
                              void* d_out, int out_size)
{
    const float* x      = (const float*)d_in[0];
    const float* w_proj = (const float*)d_in[1];
    const float* b_proj = (const float*)d_in[2];
    const float* w_ff   = (const float*)d_in[3];
    const float* b_ff   = (const float*)d_in[4];

    float* out = (float*)d_out;
    float* ff   = out;
    float* kout = out + (size_t)BATCH * SLEN * DM;
    float* vout = kout + (size_t)BATCH * NHEAD * SLEN * HS;

    cudaFuncSetAttribute(attn_mma_kernel,
                         cudaFuncAttributeMaxDynamicSharedMemorySize, ATT_SMEM);
    cudaFuncSetAttribute(gemm_bf_kernel<1>,
                         cudaFuncAttributeMaxDynamicSharedMemorySize, GEMM_SMEM);
    cudaFuncSetAttribute(gemm_bf_kernel<2>,
                         cudaFuncAttributeMaxDynamicSharedMemorySize, GEMM_SMEM);

    __nv_bfloat16 *xhi, *xlo, *wphi, *wplo, *wfhi, *wflo, *athi, *atlo;
    cudaGetSymbolAddress((void**)&xhi, g_xhi);
    cudaGetSymbolAddress((void**)&xlo, g_xlo);
    cudaGetSymbolAddress((void**)&wphi, g_wphi);
    cudaGetSymbolAddress((void**)&wplo, g_wplo);
    cudaGetSymbolAddress((void**)&wfhi, g_wfhi);
    cudaGetSymbolAddress((void**)&wflo, g_wflo);
    cudaGetSymbolAddress((void**)&athi, g_athi);
    cudaGetSymbolAddress((void**)&atlo, g_atlo);

    // 0) pre-split fp32 -> bf16 hi/lo
    split_kernel<<<2048, 256>>>((const float4*)x, (uint2*)xhi, (uint2*)xlo,
                                (BATCH * SLEN * DM) / 4);
    split_kernel<<<2048, 256>>>((const float4*)w_proj, (uint2*)wphi, (uint2*)wplo,
                                (EPROJ * DM) / 4);
    split_kernel<<<1024, 256>>>((const float4*)w_ff, (uint2*)wfhi, (uint2*)wflo,
                                (DM * DM) / 4);

    // 1) QKV projection
    gemm_bf_kernel<1><<<dim3(EPROJ / 128, (BATCH * SLEN) / 128), 256, GEMM_SMEM>>>(
        xhi, xlo, wphi, wplo, b_proj, (float*)nullptr, kout, vout);

    // 2) Causal flash attention (mma.sync) -> g_athi/g_atlo
    attn_mma_kernel<<<dim3(SLEN / QT, BATCH * NHEAD), 256, ATT_SMEM>>>();

    // 3) FF projection
    gemm_bf_kernel<2><<<dim3(DM / 128, (BATCH * SLEN) / 128), 256, GEMM_SMEM>>>(
        athi, atlo, wfhi, wflo, b_ff, ff, (float*)nullptr, (float*)nullptr);
}

// round 8
// speedup vs baseline: 1.0720x; 1.0720x over previous
#include <cuda_runtime.h>
#include <cuda_bf16.h>
#include <math.h>
#include <stdint.h>

#define BATCH 4
#define SLEN 2048
#define DM 2048
#define NHEAD 16
#define HS 128
#define EPROJ (3 * DM)
#define KDIM 2048

// Scratch (no allocations allowed)
__device__ __nv_bfloat16 g_qhi[(size_t)BATCH * NHEAD * SLEN * HS];
__device__ __nv_bfloat16 g_qlo[(size_t)BATCH * NHEAD * SLEN * HS];
__device__ __nv_bfloat16 g_khi[(size_t)BATCH * NHEAD * SLEN * HS];
__device__ __nv_bfloat16 g_klo[(size_t)BATCH * NHEAD * SLEN * HS];
__device__ __nv_bfloat16 g_vhi[(size_t)BATCH * NHEAD * SLEN * HS];
__device__ __nv_bfloat16 g_vlo[(size_t)BATCH * NHEAD * SLEN * HS];
__device__ __nv_bfloat16 g_xhi[(size_t)BATCH * SLEN * DM];
__device__ __nv_bfloat16 g_xlo[(size_t)BATCH * SLEN * DM];
__device__ __nv_bfloat16 g_wphi[(size_t)EPROJ * DM];
__device__ __nv_bfloat16 g_wplo[(size_t)EPROJ * DM];
__device__ __nv_bfloat16 g_wfhi[(size_t)DM * DM];
__device__ __nv_bfloat16 g_wflo[(size_t)DM * DM];
__device__ __nv_bfloat16 g_athi[(size_t)BATCH * SLEN * DM];
__device__ __nv_bfloat16 g_atlo[(size_t)BATCH * SLEN * DM];

// ---------------------------------------------------------------------------
// helpers (non-arch-specific PTX only)
// ---------------------------------------------------------------------------
__device__ __forceinline__ uint32_t smem_u32(const void* p) {
    uint32_t a;
    asm("{ .reg .u64 t; cvta.to.shared.u64 t, %1; cvt.u32.u64 %0, t; }"
        : "=r"(a) : "l"(p));
    return a;
}

__device__ __forceinline__ void ldm_x4(uint32_t* r, uint32_t addr) {
    asm volatile("ldmatrix.sync.aligned.m8n8.x4.shared.b16 {%0,%1,%2,%3}, [%4];"
                 : "=r"(r[0]), "=r"(r[1]), "=r"(r[2]), "=r"(r[3]) : "r"(addr));
}

__device__ __forceinline__ void ldm_x4_t(uint32_t* r, uint32_t addr) {
    asm volatile("ldmatrix.sync.aligned.m8n8.x4.trans.shared.b16 {%0,%1,%2,%3}, [%4];"
                 : "=r"(r[0]), "=r"(r[1]), "=r"(r[2]), "=r"(r[3]) : "r"(addr));
}

__device__ __forceinline__ void mma_bf16(float* c, const uint32_t* a,
                                         const uint32_t* b) {
    asm volatile(
        "mma.sync.aligned.m16n8k16.row.col.f32.bf16.bf16.f32 "
        "{%0,%1,%2,%3}, {%4,%5,%6,%7}, {%8,%9}, {%0,%1,%2,%3};"
        : "+f"(c[0]), "+f"(c[1]), "+f"(c[2]), "+f"(c[3])
        : "r"(a[0]), "r"(a[1]), "r"(a[2]), "r"(a[3]), "r"(b[0]), "r"(b[1]));
}

#define CP_ASYNC16(dst, src) \
    asm volatile("cp.async.cg.shared.global [%0], [%1], 16;" \
                 :: "r"(dst), "l"(src))
#define CP_COMMIT() asm volatile("cp.async.commit_group;" ::: "memory")
#define CP_WAIT1() asm volatile("cp.async.wait_group 1;" ::: "memory")
#define CP_WAIT0() asm volatile("cp.async.wait_group 0;" ::: "memory")

__device__ __forceinline__ void split4(float4 v, uint2& hi, uint2& lo) {
    __nv_bfloat162 h01 = __floats2bfloat162_rn(v.x, v.y);
    __nv_bfloat162 h23 = __floats2bfloat162_rn(v.z, v.w);
    uint32_t u01 = *(uint32_t*)&h01, u23 = *(uint32_t*)&h23;
    float fx = __uint_as_float(u01 << 16);
    float fy = __uint_as_float(u01 & 0xffff0000u);
    float fz = __uint_as_float(u23 << 16);
    float fw = __uint_as_float(u23 & 0xffff0000u);
    __nv_bfloat162 l01 = __floats2bfloat162_rn(v.x - fx, v.y - fy);
    __nv_bfloat162 l23 = __floats2bfloat162_rn(v.z - fz, v.w - fw);
    hi = make_uint2(u01, u23);
    lo = make_uint2(*(uint32_t*)&l01, *(uint32_t*)&l23);
}

// fp32 -> bf16 hi/lo pre-split
__global__ __launch_bounds__(256) void split_kernel(
    const float4* __restrict__ src, uint2* __restrict__ hi,
    uint2* __restrict__ lo, int n4)
{
    int i = blockIdx.x * 256 + threadIdx.x;
    const int stride = gridDim.x * 256;
    for (; i < n4; i += stride) {
        uint2 h, l;
        split4(src[i], h, l);
        hi[i] = h;
        lo[i] = l;
    }
}

// ---------------------------------------------------------------------------
// bf16-split GEMM (R5 skeleton, pre-split operands): C = A * W^T + bias.
// CTA 128x128, 8 warps (2Mx4N), warp 64x32, BK=32 bf16. Staging is plain
// cached LDG.128 -> STS.128 (2x16B per array per thread), register prefetch.
// smem: Ahi|Alo|Whi|Wlo, 128 rows x 40 bf16 pitch (conflict-free ldmatrix).
// EPI==1: QKV epilogue (q scaled hi/lo; k/v fp32 d_out + hi/lo scratch).
// EPI==2: dense fp32 C.
// ---------------------------------------------------------------------------
#define PITCH 40
#define ARRB (128 * PITCH * 2)         // 10240 B per array

template <int EPI>
__global__ __launch_bounds__(256) void gemm_bf_kernel(
    const __nv_bfloat16* __restrict__ Ahi, const __nv_bfloat16* __restrict__ Alo,
    const __nv_bfloat16* __restrict__ Whi, const __nv_bfloat16* __restrict__ Wlo,
    const float* __restrict__ bias, float* __restrict__ C,
    float* __restrict__ kout, float* __restrict__ vout)
{
    __shared__ __align__(16) char sm_bf[4 * ARRB];   // 40960 B

    const int K = KDIM;
    const int tid = threadIdx.x;
    const int wid = tid >> 5;
    const int lid = tid & 31;
    const int m0 = blockIdx.y * 128;
    const int n0 = blockIdx.x * 128;
    const int warpM = wid >> 2;
    const int warpN = wid & 3;

    const uint32_t sbase = smem_u32(sm_bf);

    // ldmatrix lane addressing (same as R5)
    const int q = lid >> 3, rr = lid & 7;
    const uint32_t aAddr = sbase +
        (uint32_t)(((warpM * 64 + (q & 1) * 8 + rr) * PITCH + (q >> 1) * 8) * 2);
    const uint32_t bAddr = sbase +
        (uint32_t)(((warpN * 32 + (q >> 1) * 8 + rr) * PITCH + (q & 1) * 8) * 2);

    float acc[4][4][4];
#pragma unroll
    for (int i = 0; i < 4; i++)
#pragma unroll
        for (int j = 0; j < 4; j++)
#pragma unroll
            for (int r = 0; r < 4; r++) acc[i][j][r] = 0.f;

    // staging: thread -> (row = tid>>1, 16-element half = tid&1); 4 arrays.
    // 16 bf16 = 32 bytes = TWO uint4 loads/stores per array per chunk.
    const int srow = tid >> 1;
    const int shalf = tid & 1;
    const __nv_bfloat16* pAh = Ahi + (size_t)(m0 + srow) * K + shalf * 16;
    const __nv_bfloat16* pAl = Alo + (size_t)(m0 + srow) * K + shalf * 16;
    const __nv_bfloat16* pWh = Whi + (size_t)(n0 + srow) * K + shalf * 16;
    const __nv_bfloat16* pWl = Wlo + (size_t)(n0 + srow) * K + shalf * 16;
    const uint32_t sto = (uint32_t)((srow * PITCH + shalf * 16) * 2);

    uint4 ra0 = *(const uint4*)pAh,       ra1 = *(const uint4*)(pAh + 8);
    uint4 rb0 = *(const uint4*)pAl,       rb1 = *(const uint4*)(pAl + 8);
    uint4 rc0 = *(const uint4*)pWh,       rc1 = *(const uint4*)(pWh + 8);
    uint4 rd0 = *(const uint4*)pWl,       rd1 = *(const uint4*)(pWl + 8);

    for (int c = 0; c < 64; c++) {
        __syncthreads();
        *(uint4*)(sm_bf + sto) = ra0;
        *(uint4*)(sm_bf + sto + 16) = ra1;
        *(uint4*)(sm_bf + ARRB + sto) = rb0;
        *(uint4*)(sm_bf + ARRB + sto + 16) = rb1;
        *(uint4*)(sm_bf + 2 * ARRB + sto) = rc0;
        *(uint4*)(sm_bf + 2 * ARRB + sto + 16) = rc1;
        *(uint4*)(sm_bf + 3 * ARRB + sto) = rd0;
        *(uint4*)(sm_bf + 3 * ARRB + sto + 16) = rd1;
        if (c < 63) {
            const int o = (c + 1) * 32;
            ra0 = *(const uint4*)(pAh + o); ra1 = *(const uint4*)(pAh + o + 8);
            rb0 = *(const uint4*)(pAl + o); rb1 = *(const uint4*)(pAl + o + 8);
            rc0 = *(const uint4*)(pWh + o); rc1 = *(const uint4*)(pWh + o + 8);
            rd0 = *(const uint4*)(pWl + o); rd1 = *(const uint4*)(pWl + o + 8);
        }
        __syncthreads();

#pragma unroll
        for (int ks = 0; ks < 2; ks++) {
            const uint32_t kb = (uint32_t)(ks * 32);
            uint32_t ah[4][4], al[4][4], bh[2][4], bl[2][4];
#pragma unroll
            for (int mi = 0; mi < 4; mi++) {
                const uint32_t off = (uint32_t)(mi * 16 * PITCH * 2) + kb;
                ldm_x4(ah[mi], aAddr + off);
                ldm_x4(al[mi], aAddr + ARRB + off);
            }
#pragma unroll
            for (int pj = 0; pj < 2; pj++) {
                const uint32_t off = (uint32_t)(pj * 16 * PITCH * 2) + kb;
                ldm_x4(bh[pj], bAddr + 2 * ARRB + off);
                ldm_x4(bl[pj], bAddr + 3 * ARRB + off);
            }
#pragma unroll
            for (int mi = 0; mi < 4; mi++)
#pragma unroll
                for (int nj = 0; nj < 4; nj++) {
                    const uint32_t* bhp = &bh[nj >> 1][(nj & 1) * 2];
                    const uint32_t* blp = &bl[nj >> 1][(nj & 1) * 2];
                    mma_bf16(acc[mi][nj], ah[mi], bhp);
                    mma_bf16(acc[mi][nj], al[mi], bhp);
                    mma_bf16(acc[mi][nj], ah[mi], blp);
                }
        }
    }

    // Epilogue
    const int t4 = lid >> 2;
    const int t2 = (lid & 3) << 1;
    if (EPI == 1) {
        const int seg = n0 >> 7;
        const int h = (int)((unsigned)seg / 3u);
        const int which = seg - h * 3;
        __nv_bfloat16 *hib, *lob;
        float* fpb = nullptr;
        if (which == 0)      { hib = g_qhi; lob = g_qlo; }
        else if (which == 1) { hib = g_khi; lob = g_klo; fpb = kout; }
        else                 { hib = g_vhi; lob = g_vlo; fpb = vout; }
        const float scl = (which == 0) ? 0.08838834764831845f : 1.0f;
#pragma unroll
        for (int mi = 0; mi < 4; mi++) {
            const int mrow = m0 + warpM * 64 + mi * 16 + t4;
            const int bb = mrow >> 11, ss = mrow & 2047;
            const size_t i0 = (((size_t)(bb * NHEAD + h)) * SLEN + ss) * HS;
            const size_t i1 = i0 + 8 * HS;
#pragma unroll
            for (int nj = 0; nj < 4; nj++) {
                const int col = warpN * 32 + nj * 8 + t2;
                const float2 bv = *(const float2*)(bias + n0 + col);
                float x0 = acc[mi][nj][0] + bv.x, x1 = acc[mi][nj][1] + bv.y;
                float y0 = acc[mi][nj][2] + bv.x, y1 = acc[mi][nj][3] + bv.y;
                if (which != 0) {
                    *(float2*)(fpb + i0 + col) = make_float2(x0, x1);
                    *(float2*)(fpb + i1 + col) = make_float2(y0, y1);
                }
                x0 *= scl; x1 *= scl; y0 *= scl; y1 *= scl;
                __nv_bfloat162 hx = __floats2bfloat162_rn(x0, x1);
                float2 hf = __bfloat1622float2(hx);
                __nv_bfloat162 lx = __floats2bfloat162_rn(x0 - hf.x, x1 - hf.y);
                __nv_bfloat162 hy = __floats2bfloat162_rn(y0, y1);
                float2 hg = __bfloat1622float2(hy);
                __nv_bfloat162 ly = __floats2bfloat162_rn(y0 - hg.x, y1 - hg.y);
                *(__nv_bfloat162*)(hib + i0 + col) = hx;
                *(__nv_bfloat162*)(lob + i0 + col) = lx;
                *(__nv_bfloat162*)(hib + i1 + col) = hy;
                *(__nv_bfloat162*)(lob + i1 + col) = ly;
            }
        }
    } else {
#pragma unroll
        for (int mi = 0; mi < 4; mi++) {
            const int mrow = m0 + warpM * 64 + mi * 16 + t4;
            float* d0 = C + (size_t)mrow * DM + n0;
            float* d1 = C + (size_t)(mrow + 8) * DM + n0;
#pragma unroll
            for (int nj = 0; nj < 4; nj++) {
                const int col = warpN * 32 + nj * 8 + t2;
                const float2 bv = *(const float2*)(bias + n0 + col);
                *(float2*)(d0 + col) =
                    make_float2(acc[mi][nj][0] + bv.x, acc[mi][nj][1] + bv.y);
                *(float2*)(d1 + col) =
                    make_float2(acc[mi][nj][2] + bv.x, acc[mi][nj][3] + bv.y);
            }
        }
    }
}

// ---------------------------------------------------------------------------
// Flash attention via mma.sync (FA2-style), causal, bf16 2-way split on both
// QK^T and PV. CTA = 128 q-rows x one (b*H+h); epilogue -> bf16 hi/lo.
// ---------------------------------------------------------------------------
#define QT 128
#define KT 64
#define Q_BYTES 32768
#define KV_ARR 16384
#define KV_BUF (4 * KV_ARR)
#define ATT_SMEM (2 * Q_BYTES + 2 * KV_BUF)  // 196608

__device__ __forceinline__ uint32_t swz(int row, int chunk) {
    return (uint32_t)(row * 256 + ((chunk ^ (row & 7)) << 4));
}

__global__ __launch_bounds__(256) void attn_mma_kernel()
{
    extern __shared__ __align__(16) char sm[];
    const uint32_t sb = smem_u32(sm);
    const int tid = threadIdx.x, wid = tid >> 5, lane = tid & 31;
    const int qb = blockIdx.x, bh = blockIdx.y;
    const int q0 = qb * QT;
    const int nkt = 2 * qb + 2;

    const size_t qoff = ((size_t)bh * SLEN + q0) * HS;
    const size_t kvoff = (size_t)bh * SLEN * HS;

    {
        const int half = tid >> 7;
        const __nv_bfloat16* src = (half ? g_qlo : g_qhi) + qoff;
        char* base = sm + half * Q_BYTES;
        int rc = tid & 127;
#pragma unroll
        for (int t = 0; t < 16; t++, rc += 128) {
            const int row = rc >> 4, c = rc & 15;
            uint4 v = *(const uint4*)(src + row * HS + c * 8);
            *(uint4*)(base + swz(row, c)) = v;
        }
    }

    const int karr = tid >> 6;
    const __nv_bfloat16* ksrc =
        ((karr == 0) ? g_khi : (karr == 1) ? g_klo : (karr == 2) ? g_vhi : g_vlo)
        + kvoff;
    const uint32_t kdstArr = sb + 2 * Q_BYTES + (uint32_t)(karr * KV_ARR);

    auto kv_issue = [&](int kt, int bf) {
        const __nv_bfloat16* s = ksrc + (size_t)kt * KT * HS;
        const uint32_t dbase = kdstArr + (uint32_t)(bf * KV_BUF);
        int rc = tid & 63;
#pragma unroll
        for (int t = 0; t < 16; t++, rc += 64) {
            const int row = rc >> 4, c = rc & 15;
            CP_ASYNC16(dbase + swz(row, c), s + row * HS + c * 8);
        }
    };

    kv_issue(0, 0);
    CP_COMMIT();

    float o[16][4];
#pragma unroll
    for (int t = 0; t < 16; t++)
#pragma unroll
        for (int r = 0; r < 4; r++) o[t][r] = 0.f;
    float m0r = -INFINITY, m1r = -INFINITY, l0r = 0.f, l1r = 0.f;

    const int aRow = wid * 16 + (lane & 7) + ((lane >> 3) & 1) * 8;
    const int aCh = lane >> 4;
    const int bRowK = (lane & 7) + (lane >> 4) * 8;
    const int bChK = (lane >> 3) & 1;
    const int vRow = (lane & 7) + ((lane >> 3) & 1) * 8;
    const int vCh = lane >> 4;

    for (int kt = 0; kt < nkt; kt++) {
        if (kt + 1 < nkt) {
            kv_issue(kt + 1, (kt + 1) & 1);
            CP_COMMIT();
            CP_WAIT1();
        } else {
            CP_WAIT0();
        }
        __syncthreads();

        const uint32_t kvb = sb + 2 * Q_BYTES + (uint32_t)((kt & 1) * KV_BUF);

        float s[8][4];
#pragma unroll
        for (int nj = 0; nj < 8; nj++)
#pragma unroll
            for (int r = 0; r < 4; r++) s[nj][r] = 0.f;

#pragma unroll
        for (int ks = 0; ks < 8; ks++) {
            uint32_t qh[4], ql[4];
            const uint32_t qa = sb + swz(aRow, 2 * ks + aCh);
            ldm_x4(qh, qa);
            ldm_x4(ql, qa + Q_BYTES);
#pragma unroll
            for (int njp = 0; njp < 4; njp++) {
                uint32_t kh[4], kl[4];
                const uint32_t ka = kvb + swz(njp * 16 + bRowK, 2 * ks + bChK);
                ldm_x4(kh, ka);
                ldm_x4(kl, ka + KV_ARR);
                mma_bf16(s[2 * njp], qh, kh);
                mma_bf16(s[2 * njp], ql, kh);
                mma_bf16(s[2 * njp], qh, kl);
                mma_bf16(s[2 * njp + 1], qh, kh + 2);
                mma_bf16(s[2 * njp + 1], ql, kh + 2);
                mma_bf16(s[2 * njp + 1], qh, kl + 2);
            }
        }

        const int r0g = q0 + wid * 16 + (lane >> 2);
        if (kt >= 2 * qb) {
            const int cb = kt * KT + (lane & 3) * 2;
#pragma unroll
            for (int nj = 0; nj < 8; nj++) {
                const int c0 = cb + nj * 8;
                if (c0 > r0g)         s[nj][0] = -INFINITY;
                if (c0 + 1 > r0g)     s[nj][1] = -INFINITY;
                if (c0 > r0g + 8)     s[nj][2] = -INFINITY;
                if (c0 + 1 > r0g + 8) s[nj][3] = -INFINITY;
            }
        }

        float tm0 = -INFINITY, tm1 = -INFINITY;
#pragma unroll
        for (int nj = 0; nj < 8; nj++) {
            tm0 = fmaxf(tm0, fmaxf(s[nj][0], s[nj][1]));
            tm1 = fmaxf(tm1, fmaxf(s[nj][2], s[nj][3]));
        }
        tm0 = fmaxf(tm0, __shfl_xor_sync(0xffffffffu, tm0, 1));
        tm0 = fmaxf(tm0, __shfl_xor_sync(0xffffffffu, tm0, 2));
        tm1 = fmaxf(tm1, __shfl_xor_sync(0xffffffffu, tm1, 1));
        tm1 = fmaxf(tm1, __shfl_xor_sync(0xffffffffu, tm1, 2));
        const float mn0 = fmaxf(m0r, tm0), mn1 = fmaxf(m1r, tm1);
        const float a0 = __expf(m0r - mn0), a1 = __expf(m1r - mn1);
        m0r = mn0; m1r = mn1;

        float ls0 = 0.f, ls1 = 0.f;
        uint32_t pah[4][4], pal[4][4];
#pragma unroll
        for (int nj = 0; nj < 8; nj++) {
            const float p0 = __expf(s[nj][0] - mn0);
            const float p1 = __expf(s[nj][1] - mn0);
            const float p2 = __expf(s[nj][2] - mn1);
            const float p3 = __expf(s[nj][3] - mn1);
            ls0 += p0 + p1;
            ls1 += p2 + p3;
            __nv_bfloat162 h01 = __floats2bfloat162_rn(p0, p1);
            float2 hf01 = __bfloat1622float2(h01);
            __nv_bfloat162 lo01 = __floats2bfloat162_rn(p0 - hf01.x, p1 - hf01.y);
            __nv_bfloat162 h23 = __floats2bfloat162_rn(p2, p3);
            float2 hf23 = __bfloat1622float2(h23);
            __nv_bfloat162 lo23 = __floats2bfloat162_rn(p2 - hf23.x, p3 - hf23.y);
            const int j = nj >> 1, e = (nj & 1) * 2;
            pah[j][e] = *(uint32_t*)&h01;
            pah[j][e + 1] = *(uint32_t*)&h23;
            pal[j][e] = *(uint32_t*)&lo01;
            pal[j][e + 1] = *(uint32_t*)&lo23;
        }
        ls0 += __shfl_xor_sync(0xffffffffu, ls0, 1);
        ls0 += __shfl_xor_sync(0xffffffffu, ls0, 2);
        ls1 += __shfl_xor_sync(0xffffffffu, ls1, 1);
        ls1 += __shfl_xor_sync(0xffffffffu, ls1, 2);
        l0r = l0r * a0 + ls0;
        l1r = l1r * a1 + ls1;

#pragma unroll
        for (int t = 0; t < 16; t++) {
            o[t][0] *= a0; o[t][1] *= a0;
            o[t][2] *= a1; o[t][3] *= a1;
        }

#pragma unroll
        for (int j = 0; j < 4; j++) {
#pragma unroll
            for (int nd = 0; nd < 8; nd++) {
                uint32_t vh[4], vl[4];
                const uint32_t va =
                    kvb + 2 * KV_ARR + swz(j * 16 + vRow, 2 * nd + vCh);
                ldm_x4_t(vh, va);
                ldm_x4_t(vl, va + KV_ARR);
                mma_bf16(o[2 * nd], pah[j], vh);
                mma_bf16(o[2 * nd], pal[j], vh);
                mma_bf16(o[2 * nd], pah[j], vl);
                mma_bf16(o[2 * nd + 1], pah[j], vh + 2);
                mma_bf16(o[2 * nd + 1], pal[j], vh + 2);
                mma_bf16(o[2 * nd + 1], pah[j], vl + 2);
            }
        }
        __syncthreads();
    }

    // write attn_o as bf16 hi/lo directly (consumed by FF GEMM)
    const float inv0 = 1.f / l0r, inv1 = 1.f / l1r;
    const int b = bh >> 4, h = bh & 15;
    const int r0g = q0 + wid * 16 + (lane >> 2);
    const size_t base0 =
        ((size_t)(b * SLEN + r0g)) * DM + h * HS + (lane & 3) * 2;
    const size_t base1 = base0 + (size_t)8 * DM;
#pragma unroll
    for (int t = 0; t < 16; t++) {
        float v0 = o[t][0] * inv0, v1 = o[t][1] * inv0;
        float w0 = o[t][2] * inv1, w1 = o[t][3] * inv1;
        __nv_bfloat162 h0 = __floats2bfloat162_rn(v0, v1);
        float2 f0 = __bfloat1622float2(h0);
        __nv_bfloat162 l0 = __floats2bfloat162_rn(v0 - f0.x, v1 - f0.y);
        __nv_bfloat162 h1 = __floats2bfloat162_rn(w0, w1);
        float2 f1 = __bfloat1622float2(h1);
        __nv_bfloat162 l1 = __floats2bfloat162_rn(w0 - f1.x, w1 - f1.y);
        *(__nv_bfloat162*)(g_athi + base0 + t * 8) = h0;
        *(__nv_bfloat162*)(g_atlo + base0 + t * 8) = l0;
        *(__nv_bfloat162*)(g_athi + base1 + t * 8) = h1;
        *(__nv_bfloat162*)(g_atlo + base1 + t * 8) = l1;
    }
}

// ---------------------------------------------------------------------------
extern "C" void kernel_launch(void* const* d_in, const int* in_sizes, int n_in,
                              void* d_out, int out_size)
{
    const float* x      = (const float*)d_in[0];
    const float* w_proj = (const float*)d_in[1];
    const float* b_proj = (const float*)d_in[2];
    const float* w_ff   = (const float*)d_in[3];
    const float* b_ff   = (const float*)d_in[4];

    float* out = (float*)d_out;
    float* ff   = out;
    float* kout = out + (size_t)BATCH * SLEN * DM;
    float* vout = kout + (size_t)BATCH * NHEAD * SLEN * HS;

    cudaFuncSetAttribute(attn_mma_kernel,
                         cudaFuncAttributeMaxDynamicSharedMemorySize, ATT_SMEM);

    __nv_bfloat16 *xhi, *xlo, *wphi, *wplo, *wfhi, *wflo, *athi, *atlo;
    cudaGetSymbolAddress((void**)&xhi, g_xhi);
    cudaGetSymbolAddress((void**)&xlo, g_xlo);
    cudaGetSymbolAddress((void**)&wphi, g_wphi);
    cudaGetSymbolAddress((void**)&wplo, g_wplo);
    cudaGetSymbolAddress((void**)&wfhi, g_wfhi);
    cudaGetSymbolAddress((void**)&wflo, g_wflo);
    cudaGetSymbolAddress((void**)&athi, g_athi);
    cudaGetSymbolAddress((void**)&atlo, g_atlo);

    // 0) pre-split fp32 -> bf16 hi/lo
    split_kernel<<<2048, 256>>>((const float4*)x, (uint2*)xhi, (uint2*)xlo,
                                (BATCH * SLEN * DM) / 4);
    split_kernel<<<2048, 256>>>((const float4*)w_proj, (uint2*)wphi, (uint2*)wplo,
                                (EPROJ * DM) / 4);
    split_kernel<<<1024, 256>>>((const float4*)w_ff, (uint2*)wfhi, (uint2*)wflo,
                                (DM * DM) / 4);

    // 1) QKV projection
    gemm_bf_kernel<1><<<dim3(EPROJ / 128, (BATCH * SLEN) / 128), 256>>>(
        xhi, xlo, wphi, wplo, b_proj, (float*)nullptr, kout, vout);

    // 2) Causal flash attention (mma.sync) -> g_athi/g_atlo
    attn_mma_kernel<<<dim3(SLEN / QT, BATCH * NHEAD), 256, ATT_SMEM>>>();

    // 3) FF projection
    gemm_bf_kernel<2><<<dim3(DM / 128, (BATCH * SLEN) / 128), 256>>>(
        athi, atlo, wfhi, wflo, b_ff, ff, (float*)nullptr, (float*)nullptr);
}

// round 9
// speedup vs baseline: 1.1060x; 1.0318x over previous
#include <cuda_runtime.h>
#include <cuda_bf16.h>
#include <math.h>
#include <stdint.h>

#define BATCH 4
#define SLEN 2048
#define DM 2048
#define NHEAD 16
#define HS 128
#define EPROJ (3 * DM)
#define KDIM 2048

// Scratch (no allocations allowed)
__device__ __nv_bfloat16 g_qhi[(size_t)BATCH * NHEAD * SLEN * HS];
__device__ __nv_bfloat16 g_qlo[(size_t)BATCH * NHEAD * SLEN * HS];
__device__ __nv_bfloat16 g_khi[(size_t)BATCH * NHEAD * SLEN * HS];
__device__ __nv_bfloat16 g_klo[(size_t)BATCH * NHEAD * SLEN * HS];
__device__ __nv_bfloat16 g_vhi[(size_t)BATCH * NHEAD * SLEN * HS];
__device__ __nv_bfloat16 g_vlo[(size_t)BATCH * NHEAD * SLEN * HS];
__device__ __nv_bfloat16 g_xhi[(size_t)BATCH * SLEN * DM];
__device__ __nv_bfloat16 g_xlo[(size_t)BATCH * SLEN * DM];
__device__ __nv_bfloat16 g_wphi[(size_t)EPROJ * DM];
__device__ __nv_bfloat16 g_wplo[(size_t)EPROJ * DM];
__device__ __nv_bfloat16 g_wfhi[(size_t)DM * DM];
__device__ __nv_bfloat16 g_wflo[(size_t)DM * DM];
__device__ __nv_bfloat16 g_athi[(size_t)BATCH * SLEN * DM];
__device__ __nv_bfloat16 g_atlo[(size_t)BATCH * SLEN * DM];

// ---------------------------------------------------------------------------
// helpers (non-arch-specific PTX only)
// ---------------------------------------------------------------------------
__device__ __forceinline__ uint32_t smem_u32(const void* p) {
    uint32_t a;
    asm("{ .reg .u64 t; cvta.to.shared.u64 t, %1; cvt.u32.u64 %0, t; }"
        : "=r"(a) : "l"(p));
    return a;
}

__device__ __forceinline__ void ldm_x4(uint32_t* r, uint32_t addr) {
    asm volatile("ldmatrix.sync.aligned.m8n8.x4.shared.b16 {%0,%1,%2,%3}, [%4];"
                 : "=r"(r[0]), "=r"(r[1]), "=r"(r[2]), "=r"(r[3]) : "r"(addr));
}

__device__ __forceinline__ void ldm_x4_t(uint32_t* r, uint32_t addr) {
    asm volatile("ldmatrix.sync.aligned.m8n8.x4.trans.shared.b16 {%0,%1,%2,%3}, [%4];"
                 : "=r"(r[0]), "=r"(r[1]), "=r"(r[2]), "=r"(r[3]) : "r"(addr));
}

__device__ __forceinline__ void mma_bf16(float* c, const uint32_t* a,
                                         const uint32_t* b) {
    asm volatile(
        "mma.sync.aligned.m16n8k16.row.col.f32.bf16.bf16.f32 "
        "{%0,%1,%2,%3}, {%4,%5,%6,%7}, {%8,%9}, {%0,%1,%2,%3};"
        : "+f"(c[0]), "+f"(c[1]), "+f"(c[2]), "+f"(c[3])
        : "r"(a[0]), "r"(a[1]), "r"(a[2]), "r"(a[3]), "r"(b[0]), "r"(b[1]));
}

#define CP_ASYNC16(dst, src) \
    asm volatile("cp.async.cg.shared.global [%0], [%1], 16;" \
                 :: "r"(dst), "l"(src))
#define CP_COMMIT() asm volatile("cp.async.commit_group;" ::: "memory")
#define CP_WAIT1() asm volatile("cp.async.wait_group 1;" ::: "memory")
#define CP_WAIT0() asm volatile("cp.async.wait_group 0;" ::: "memory")

__device__ __forceinline__ void split4(float4 v, uint2& hi, uint2& lo) {
    __nv_bfloat162 h01 = __floats2bfloat162_rn(v.x, v.y);
    __nv_bfloat162 h23 = __floats2bfloat162_rn(v.z, v.w);
    uint32_t u01 = *(uint32_t*)&h01, u23 = *(uint32_t*)&h23;
    float fx = __uint_as_float(u01 << 16);
    float fy = __uint_as_float(u01 & 0xffff0000u);
    float fz = __uint_as_float(u23 << 16);
    float fw = __uint_as_float(u23 & 0xffff0000u);
    __nv_bfloat162 l01 = __floats2bfloat162_rn(v.x - fx, v.y - fy);
    __nv_bfloat162 l23 = __floats2bfloat162_rn(v.z - fz, v.w - fw);
    hi = make_uint2(u01, u23);
    lo = make_uint2(*(uint32_t*)&l01, *(uint32_t*)&l23);
}

// fp32 -> bf16 hi/lo pre-split
__global__ __launch_bounds__(256) void split_kernel(
    const float4* __restrict__ src, uint2* __restrict__ hi,
    uint2* __restrict__ lo, int n4)
{
    int i = blockIdx.x * 256 + threadIdx.x;
    const int stride = gridDim.x * 256;
    for (; i < n4; i += stride) {
        uint2 h, l;
        split4(src[i], h, l);
        hi[i] = h;
        lo[i] = l;
    }
}

// ---------------------------------------------------------------------------
// bf16-split GEMM: C = A * W^T + bias (pre-split hi/lo operands).
// CTA 128x128, 8 warps (2Mx4N), warp 64x32, BK=32. Cached LDG.128 -> STS.128
// staging with register prefetch. smem 40KB, regs capped for 2 CTAs/SM.
// EPI==1: QKV epilogue (q scaled hi/lo; k/v fp32 d_out + hi/lo scratch).
// EPI==2: dense fp32 C.
// ---------------------------------------------------------------------------
#define PITCH 40
#define ARRB (128 * PITCH * 2)         // 10240 B per array

template <int EPI>
__global__ __launch_bounds__(256, 2) void gemm_bf_kernel(
    const __nv_bfloat16* __restrict__ Ahi, const __nv_bfloat16* __restrict__ Alo,
    const __nv_bfloat16* __restrict__ Whi, const __nv_bfloat16* __restrict__ Wlo,
    const float* __restrict__ bias, float* __restrict__ C,
    float* __restrict__ kout, float* __restrict__ vout)
{
    __shared__ __align__(16) char sm_bf[4 * ARRB];   // 40960 B

    const int K = KDIM;
    const int tid = threadIdx.x;
    const int wid = tid >> 5;
    const int lid = tid & 31;
    const int m0 = blockIdx.y * 128;
    const int n0 = blockIdx.x * 128;
    const int warpM = wid >> 2;
    const int warpN = wid & 3;

    const uint32_t sbase = smem_u32(sm_bf);

    // ldmatrix lane addressing
    const int q = lid >> 3, rr = lid & 7;
    const uint32_t aAddr = sbase +
        (uint32_t)(((warpM * 64 + (q & 1) * 8 + rr) * PITCH + (q >> 1) * 8) * 2);
    const uint32_t bAddr = sbase +
        (uint32_t)(((warpN * 32 + (q >> 1) * 8 + rr) * PITCH + (q & 1) * 8) * 2);

    float acc[4][4][4];
#pragma unroll
    for (int i = 0; i < 4; i++)
#pragma unroll
        for (int j = 0; j < 4; j++)
#pragma unroll
            for (int r = 0; r < 4; r++) acc[i][j][r] = 0.f;

    // staging: thread -> (row = tid>>1, 16-element half = tid&1); 4 arrays.
    const int srow = tid >> 1;
    const int shalf = tid & 1;
    const __nv_bfloat16* pAh = Ahi + (size_t)(m0 + srow) * K + shalf * 16;
    const __nv_bfloat16* pAl = Alo + (size_t)(m0 + srow) * K + shalf * 16;
    const __nv_bfloat16* pWh = Whi + (size_t)(n0 + srow) * K + shalf * 16;
    const __nv_bfloat16* pWl = Wlo + (size_t)(n0 + srow) * K + shalf * 16;
    const uint32_t sto = (uint32_t)((srow * PITCH + shalf * 16) * 2);

    uint4 ra0 = *(const uint4*)pAh,       ra1 = *(const uint4*)(pAh + 8);
    uint4 rb0 = *(const uint4*)pAl,       rb1 = *(const uint4*)(pAl + 8);
    uint4 rc0 = *(const uint4*)pWh,       rc1 = *(const uint4*)(pWh + 8);
    uint4 rd0 = *(const uint4*)pWl,       rd1 = *(const uint4*)(pWl + 8);

    for (int c = 0; c < 64; c++) {
        __syncthreads();
        *(uint4*)(sm_bf + sto) = ra0;
        *(uint4*)(sm_bf + sto + 16) = ra1;
        *(uint4*)(sm_bf + ARRB + sto) = rb0;
        *(uint4*)(sm_bf + ARRB + sto + 16) = rb1;
        *(uint4*)(sm_bf + 2 * ARRB + sto) = rc0;
        *(uint4*)(sm_bf + 2 * ARRB + sto + 16) = rc1;
        *(uint4*)(sm_bf + 3 * ARRB + sto) = rd0;
        *(uint4*)(sm_bf + 3 * ARRB + sto + 16) = rd1;
        if (c < 63) {
            const int o = (c + 1) * 32;
            ra0 = *(const uint4*)(pAh + o); ra1 = *(const uint4*)(pAh + o + 8);
            rb0 = *(const uint4*)(pAl + o); rb1 = *(const uint4*)(pAl + o + 8);
            rc0 = *(const uint4*)(pWh + o); rc1 = *(const uint4*)(pWh + o + 8);
            rd0 = *(const uint4*)(pWl + o); rd1 = *(const uint4*)(pWl + o + 8);
        }
        __syncthreads();

#pragma unroll
        for (int ks = 0; ks < 2; ks++) {
            const uint32_t kb = (uint32_t)(ks * 32);
            uint32_t ah[4][4], al[4][4], bh[2][4], bl[2][4];
#pragma unroll
            for (int mi = 0; mi < 4; mi++) {
                const uint32_t off = (uint32_t)(mi * 16 * PITCH * 2) + kb;
                ldm_x4(ah[mi], aAddr + off);
                ldm_x4(al[mi], aAddr + ARRB + off);
            }
#pragma unroll
            for (int pj = 0; pj < 2; pj++) {
                const uint32_t off = (uint32_t)(pj * 16 * PITCH * 2) + kb;
                ldm_x4(bh[pj], bAddr + 2 * ARRB + off);
                ldm_x4(bl[pj], bAddr + 3 * ARRB + off);
            }
#pragma unroll
            for (int mi = 0; mi < 4; mi++)
#pragma unroll
                for (int nj = 0; nj < 4; nj++) {
                    const uint32_t* bhp = &bh[nj >> 1][(nj & 1) * 2];
                    const uint32_t* blp = &bl[nj >> 1][(nj & 1) * 2];
                    mma_bf16(acc[mi][nj], ah[mi], bhp);
                    mma_bf16(acc[mi][nj], al[mi], bhp);
                    mma_bf16(acc[mi][nj], ah[mi], blp);
                }
        }
    }

    // Epilogue
    const int t4 = lid >> 2;
    const int t2 = (lid & 3) << 1;
    if (EPI == 1) {
        const int seg = n0 >> 7;
        const int h = (int)((unsigned)seg / 3u);
        const int which = seg - h * 3;
        __nv_bfloat16 *hib, *lob;
        float* fpb = nullptr;
        if (which == 0)      { hib = g_qhi; lob = g_qlo; }
        else if (which == 1) { hib = g_khi; lob = g_klo; fpb = kout; }
        else                 { hib = g_vhi; lob = g_vlo; fpb = vout; }
        const float scl = (which == 0) ? 0.08838834764831845f : 1.0f;
#pragma unroll
        for (int mi = 0; mi < 4; mi++) {
            const int mrow = m0 + warpM * 64 + mi * 16 + t4;
            const int bb = mrow >> 11, ss = mrow & 2047;
            const size_t i0 = (((size_t)(bb * NHEAD + h)) * SLEN + ss) * HS;
            const size_t i1 = i0 + 8 * HS;
#pragma unroll
            for (int nj = 0; nj < 4; nj++) {
                const int col = warpN * 32 + nj * 8 + t2;
                const float2 bv = *(const float2*)(bias + n0 + col);
                float x0 = acc[mi][nj][0] + bv.x, x1 = acc[mi][nj][1] + bv.y;
                float y0 = acc[mi][nj][2] + bv.x, y1 = acc[mi][nj][3] + bv.y;
                if (which != 0) {
                    *(float2*)(fpb + i0 + col) = make_float2(x0, x1);
                    *(float2*)(fpb + i1 + col) = make_float2(y0, y1);
                }
                x0 *= scl; x1 *= scl; y0 *= scl; y1 *= scl;
                __nv_bfloat162 hx = __floats2bfloat162_rn(x0, x1);
                float2 hf = __bfloat1622float2(hx);
                __nv_bfloat162 lx = __floats2bfloat162_rn(x0 - hf.x, x1 - hf.y);
                __nv_bfloat162 hy = __floats2bfloat162_rn(y0, y1);
                float2 hg = __bfloat1622float2(hy);
                __nv_bfloat162 ly = __floats2bfloat162_rn(y0 - hg.x, y1 - hg.y);
                *(__nv_bfloat162*)(hib + i0 + col) = hx;
                *(__nv_bfloat162*)(lob + i0 + col) = lx;
                *(__nv_bfloat162*)(hib + i1 + col) = hy;
                *(__nv_bfloat162*)(lob + i1 + col) = ly;
            }
        }
    } else {
#pragma unroll
        for (int mi = 0; mi < 4; mi++) {
            const int mrow = m0 + warpM * 64 + mi * 16 + t4;
            float* d0 = C + (size_t)mrow * DM + n0;
            float* d1 = C + (size_t)(mrow + 8) * DM + n0;
#pragma unroll
            for (int nj = 0; nj < 4; nj++) {
                const int col = warpN * 32 + nj * 8 + t2;
                const float2 bv = *(const float2*)(bias + n0 + col);
                *(float2*)(d0 + col) =
                    make_float2(acc[mi][nj][0] + bv.x, acc[mi][nj][1] + bv.y);
                *(float2*)(d1 + col) =
                    make_float2(acc[mi][nj][2] + bv.x, acc[mi][nj][3] + bv.y);
            }
        }
    }
}

// ---------------------------------------------------------------------------
// Flash attention via mma.sync (FA2-style), causal, bf16 2-way split on both
// QK^T and PV. CTA = 128 q-rows x one (b*H+h); epilogue -> bf16 hi/lo.
// ---------------------------------------------------------------------------
#define QT 128
#define KT 64
#define Q_BYTES 32768
#define KV_ARR 16384
#define KV_BUF (4 * KV_ARR)
#define ATT_SMEM (2 * Q_BYTES + 2 * KV_BUF)  // 196608

__device__ __forceinline__ uint32_t swz(int row, int chunk) {
    return (uint32_t)(row * 256 + ((chunk ^ (row & 7)) << 4));
}

__global__ __launch_bounds__(256) void attn_mma_kernel()
{
    extern __shared__ __align__(16) char sm[];
    const uint32_t sb = smem_u32(sm);
    const int tid = threadIdx.x, wid = tid >> 5, lane = tid & 31;
    const int qb = blockIdx.x, bh = blockIdx.y;
    const int q0 = qb * QT;
    const int nkt = 2 * qb + 2;

    const size_t qoff = ((size_t)bh * SLEN + q0) * HS;
    const size_t kvoff = (size_t)bh * SLEN * HS;

    {
        const int half = tid >> 7;
        const __nv_bfloat16* src = (half ? g_qlo : g_qhi) + qoff;
        char* base = sm + half * Q_BYTES;
        int rc = tid & 127;
#pragma unroll
        for (int t = 0; t < 16; t++, rc += 128) {
            const int row = rc >> 4, c = rc & 15;
            uint4 v = *(const uint4*)(src + row * HS + c * 8);
            *(uint4*)(base + swz(row, c)) = v;
        }
    }

    const int karr = tid >> 6;
    const __nv_bfloat16* ksrc =
        ((karr == 0) ? g_khi : (karr == 1) ? g_klo : (karr == 2) ? g_vhi : g_vlo)
        + kvoff;
    const uint32_t kdstArr = sb + 2 * Q_BYTES + (uint32_t)(karr * KV_ARR);

    auto kv_issue = [&](int kt, int bf) {
        const __nv_bfloat16* s = ksrc + (size_t)kt * KT * HS;
        const uint32_t dbase = kdstArr + (uint32_t)(bf * KV_BUF);
        int rc = tid & 63;
#pragma unroll
        for (int t = 0; t < 16; t++, rc += 64) {
            const int row = rc >> 4, c = rc & 15;
            CP_ASYNC16(dbase + swz(row, c), s + row * HS + c * 8);
        }
    };

    kv_issue(0, 0);
    CP_COMMIT();

    float o[16][4];
#pragma unroll
    for (int t = 0; t < 16; t++)
#pragma unroll
        for (int r = 0; r < 4; r++) o[t][r] = 0.f;
    float m0r = -INFINITY, m1r = -INFINITY, l0r = 0.f, l1r = 0.f;

    const int aRow = wid * 16 + (lane & 7) + ((lane >> 3) & 1) * 8;
    const int aCh = lane >> 4;
    const int bRowK = (lane & 7) + (lane >> 4) * 8;
    const int bChK = (lane >> 3) & 1;
    const int vRow = (lane & 7) + ((lane >> 3) & 1) * 8;
    const int vCh = lane >> 4;

    for (int kt = 0; kt < nkt; kt++) {
        if (kt + 1 < nkt) {
            kv_issue(kt + 1, (kt + 1) & 1);
            CP_COMMIT();
            CP_WAIT1();
        } else {
            CP_WAIT0();
        }
        __syncthreads();

        const uint32_t kvb = sb + 2 * Q_BYTES + (uint32_t)((kt & 1) * KV_BUF);

        float s[8][4];
#pragma unroll
        for (int nj = 0; nj < 8; nj++)
#pragma unroll
            for (int r = 0; r < 4; r++) s[nj][r] = 0.f;

#pragma unroll
        for (int ks = 0; ks < 8; ks++) {
            uint32_t qh[4], ql[4];
            const uint32_t qa = sb + swz(aRow, 2 * ks + aCh);
            ldm_x4(qh, qa);
            ldm_x4(ql, qa + Q_BYTES);
#pragma unroll
            for (int njp = 0; njp < 4; njp++) {
                uint32_t kh[4], kl[4];
                const uint32_t ka = kvb + swz(njp * 16 + bRowK, 2 * ks + bChK);
                ldm_x4(kh, ka);
                ldm_x4(kl, ka + KV_ARR);
                mma_bf16(s[2 * njp], qh, kh);
                mma_bf16(s[2 * njp], ql, kh);
                mma_bf16(s[2 * njp], qh, kl);
                mma_bf16(s[2 * njp + 1], qh, kh + 2);
                mma_bf16(s[2 * njp + 1], ql, kh + 2);
                mma_bf16(s[2 * njp + 1], qh, kl + 2);
            }
        }

        const int r0g = q0 + wid * 16 + (lane >> 2);
        if (kt >= 2 * qb) {
            const int cb = kt * KT + (lane & 3) * 2;
#pragma unroll
            for (int nj = 0; nj < 8; nj++) {
                const int c0 = cb + nj * 8;
                if (c0 > r0g)         s[nj][0] = -INFINITY;
                if (c0 + 1 > r0g)     s[nj][1] = -INFINITY;
                if (c0 > r0g + 8)     s[nj][2] = -INFINITY;
                if (c0 + 1 > r0g + 8) s[nj][3] = -INFINITY;
            }
        }

        float tm0 = -INFINITY, tm1 = -INFINITY;
#pragma unroll
        for (int nj = 0; nj < 8; nj++) {
            tm0 = fmaxf(tm0, fmaxf(s[nj][0], s[nj][1]));
            tm1 = fmaxf(tm1, fmaxf(s[nj][2], s[nj][3]));
        }
        tm0 = fmaxf(tm0, __shfl_xor_sync(0xffffffffu, tm0, 1));
        tm0 = fmaxf(tm0, __shfl_xor_sync(0xffffffffu, tm0, 2));
        tm1 = fmaxf(tm1, __shfl_xor_sync(0xffffffffu, tm1, 1));
        tm1 = fmaxf(tm1, __shfl_xor_sync(0xffffffffu, tm1, 2));
        const float mn0 = fmaxf(m0r, tm0), mn1 = fmaxf(m1r, tm1);
        const float a0 = __expf(m0r - mn0), a1 = __expf(m1r - mn1);
        m0r = mn0; m1r = mn1;

        float ls0 = 0.f, ls1 = 0.f;
        uint32_t pah[4][4], pal[4][4];
#pragma unroll
        for (int nj = 0; nj < 8; nj++) {
            const float p0 = __expf(s[nj][0] - mn0);
            const float p1 = __expf(s[nj][1] - mn0);
            const float p2 = __expf(s[nj][2] - mn1);
            const float p3 = __expf(s[nj][3] - mn1);
            ls0 += p0 + p1;
            ls1 += p2 + p3;
            __nv_bfloat162 h01 = __floats2bfloat162_rn(p0, p1);
            float2 hf01 = __bfloat1622float2(h01);
            __nv_bfloat162 lo01 = __floats2bfloat162_rn(p0 - hf01.x, p1 - hf01.y);
            __nv_bfloat162 h23 = __floats2bfloat162_rn(p2, p3);
            float2 hf23 = __bfloat1622float2(h23);
            __nv_bfloat162 lo23 = __floats2bfloat162_rn(p2 - hf23.x, p3 - hf23.y);
            const int j = nj >> 1, e = (nj & 1) * 2;
            pah[j][e] = *(uint32_t*)&h01;
            pah[j][e + 1] = *(uint32_t*)&h23;
            pal[j][e] = *(uint32_t*)&lo01;
            pal[j][e + 1] = *(uint32_t*)&lo23;
        }
        ls0 += __shfl_xor_sync(0xffffffffu, ls0, 1);
        ls0 += __shfl_xor_sync(0xffffffffu, ls0, 2);
        ls1 += __shfl_xor_sync(0xffffffffu, ls1, 1);
        ls1 += __shfl_xor_sync(0xffffffffu, ls1, 2);
        l0r = l0r * a0 + ls0;
        l1r = l1r * a1 + ls1;

#pragma unroll
        for (int t = 0; t < 16; t++) {
            o[t][0] *= a0; o[t][1] *= a0;
            o[t][2] *= a1; o[t][3] *= a1;
        }

#pragma unroll
        for (int j = 0; j < 4; j++) {
#pragma unroll
            for (int nd = 0; nd < 8; nd++) {
                uint32_t vh[4], vl[4];
                const uint32_t va =
                    kvb + 2 * KV_ARR + swz(j * 16 + vRow, 2 * nd + vCh);
                ldm_x4_t(vh, va);
                ldm_x4_t(vl, va + KV_ARR);
                mma_bf16(o[2 * nd], pah[j], vh);
                mma_bf16(o[2 * nd], pal[j], vh);
                mma_bf16(o[2 * nd], pah[j], vl);
                mma_bf16(o[2 * nd + 1], pah[j], vh + 2);
                mma_bf16(o[2 * nd + 1], pal[j], vh + 2);
                mma_bf16(o[2 * nd + 1], pah[j], vl + 2);
            }
        }
        __syncthreads();
    }

    // write attn_o as bf16 hi/lo directly (consumed by FF GEMM)
    const float inv0 = 1.f / l0r, inv1 = 1.f / l1r;
    const int b = bh >> 4, h = bh & 15;
    const int r0g = q0 + wid * 16 + (lane >> 2);
    const size_t base0 =
        ((size_t)(b * SLEN + r0g)) * DM + h * HS + (lane & 3) * 2;
    const size_t base1 = base0 + (size_t)8 * DM;
#pragma unroll
    for (int t = 0; t < 16; t++) {
        float v0 = o[t][0] * inv0, v1 = o[t][1] * inv0;
        float w0 = o[t][2] * inv1, w1 = o[t][3] * inv1;
        __nv_bfloat162 h0 = __floats2bfloat162_rn(v0, v1);
        float2 f0 = __bfloat1622float2(h0);
        __nv_bfloat162 l0 = __floats2bfloat162_rn(v0 - f0.x, v1 - f0.y);
        __nv_bfloat162 h1 = __floats2bfloat162_rn(w0, w1);
        float2 f1 = __bfloat1622float2(h1);
        __nv_bfloat162 l1 = __floats2bfloat162_rn(w0 - f1.x, w1 - f1.y);
        *(__nv_bfloat162*)(g_athi + base0 + t * 8) = h0;
        *(__nv_bfloat162*)(g_atlo + base0 + t * 8) = l0;
        *(__nv_bfloat162*)(g_athi + base1 + t * 8) = h1;
        *(__nv_bfloat162*)(g_atlo + base1 + t * 8) = l1;
    }
}

// ---------------------------------------------------------------------------
extern "C" void kernel_launch(void* const* d_in, const int* in_sizes, int n_in,
                              void* d_out, int out_size)
{
    const float* x      = (const float*)d_in[0];
    const float* w_proj = (const float*)d_in[1];
    const float* b_proj = (const float*)d_in[2];
    const float* w_ff   = (const float*)d_in[3];
    const float* b_ff   = (const float*)d_in[4];

    float* out = (float*)d_out;
    float* ff   = out;
    float* kout = out + (size_t)BATCH * SLEN * DM;
    float* vout = kout + (size_t)BATCH * NHEAD * SLEN * HS;

    cudaFuncSetAttribute(attn_mma_kernel,
                         cudaFuncAttributeMaxDynamicSharedMemorySize, ATT_SMEM);

    __nv_bfloat16 *xhi, *xlo, *wphi, *wplo, *wfhi, *wflo, *athi, *atlo;
    cudaGetSymbolAddress((void**)&xhi, g_xhi);
    cudaGetSymbolAddress((void**)&xlo, g_xlo);
    cudaGetSymbolAddress((void**)&wphi, g_wphi);
    cudaGetSymbolAddress((void**)&wplo, g_wplo);
    cudaGetSymbolAddress((void**)&wfhi, g_wfhi);
    cudaGetSymbolAddress((void**)&wflo, g_wflo);
    cudaGetSymbolAddress((void**)&athi, g_athi);
    cudaGetSymbolAddress((void**)&atlo, g_atlo);

    // 0) pre-split fp32 -> bf16 hi/lo
    split_kernel<<<2048, 256>>>((const float4*)x, (uint2*)xhi, (uint2*)xlo,
                                (BATCH * SLEN * DM) / 4);
    split_kernel<<<2048, 256>>>((const float4*)w_proj, (uint2*)wphi, (uint2*)wplo,
                                (EPROJ * DM) / 4);
    split_kernel<<<1024, 256>>>((const float4*)w_ff, (uint2*)wfhi, (uint2*)wflo,
                                (DM * DM) / 4);

    // 1) QKV projection
    gemm_bf_kernel<1><<<dim3(EPROJ / 128, (BATCH * SLEN) / 128), 256>>>(
        xhi, xlo, wphi, wplo, b_proj, (float*)nullptr, kout, vout);

    // 2) Causal flash attention (mma.sync) -> g_athi/g_atlo
    attn_mma_kernel<<<dim3(SLEN / QT, BATCH * NHEAD), 256, ATT_SMEM>>>();

    // 3) FF projection
    gemm_bf_kernel<2><<<dim3(DM / 128, (BATCH * SLEN) / 128), 256>>>(
        athi, atlo, wfhi, wflo, b_ff, ff, (float*)nullptr, (float*)nullptr);
}